// round 7
// baseline (speedup 1.0000x reference)
#include <cuda_runtime.h>
#include <cuda_fp16.h>

#define BH   16
#define LQ   512
#define LK   512
#define DD   64
#define D16  48      // d-slice on MUFU f16x2 tanh path
#define D32  16      // d-slice on FMA-pipe Pade path
#define TQ   32
#define TK   128
#define W16  25      // wk16 row stride in u32 (24 data + 1 pad, odd -> conflict-free)
#define W32  18      // wq32/wk32 row stride in floats (16 data + 2 pad, rows 8B-aligned)

// Projected tensors (device globals: no allocation).
__device__ __half2 g_Wq16[BH * LQ * D16 / 2];
__device__ __half2 g_Wk16[BH * LK * D16 / 2];
__device__ float   g_Wq32[BH * LQ * D32];
__device__ float   g_Wk32[BH * LK * D32];

// ---------------------------------------------------------------------------
// Packed helpers
// ---------------------------------------------------------------------------
__device__ __forceinline__ __half2 tanh2(__half2 x) {
    unsigned xi = *(unsigned*)&x, yi;
    asm("tanh.approx.f16x2 %0, %1;" : "=r"(yi) : "r"(xi));
    return *(__half2*)&yi;
}

__device__ __forceinline__ void acc_flush(double& acc, __half2 h) {
    unsigned hi = *(unsigned*)&h;
    asm("{\n\t"
        ".reg .f16 l, m;\n\t"
        ".reg .f32 fl, fh;\n\t"
        ".reg .b64 p;\n\t"
        "mov.b32 {l, m}, %1;\n\t"
        "cvt.f32.f16 fl, l;\n\t"
        "cvt.f32.f16 fh, m;\n\t"
        "mov.b64 p, {fl, fh};\n\t"
        "add.rn.f32x2 %0, %0, p;\n\t"
        "}" : "+d"(acc) : "r"(hi));
}

__device__ __forceinline__ double f2x2(float lo, float hi) {
    double r; asm("mov.b64 %0, {%1, %2};" : "=d"(r) : "f"(lo), "f"(hi)); return r;
}
__device__ __forceinline__ double addx2(double a, double b) {
    double r; asm("add.rn.f32x2 %0, %1, %2;" : "=d"(r) : "d"(a), "d"(b)); return r;
}
__device__ __forceinline__ double mulx2(double a, double b) {
    double r; asm("mul.rn.f32x2 %0, %1, %2;" : "=d"(r) : "d"(a), "d"(b)); return r;
}
__device__ __forceinline__ double fmx2(double a, double b, double c) {
    double r; asm("fma.rn.f32x2 %0, %1, %2, %3;" : "=d"(r) : "d"(a), "d"(b), "d"(c)); return r;
}
// Reciprocal seed of +D from bits of (-D): 0xFEF311C3 - bits(-D) == 0x7EF311C3 - bits(D).
__device__ __forceinline__ double rcp_seed_from_neg(double dn) {
    unsigned lo, hi;
    asm("mov.b64 {%0, %1}, %2;" : "=r"(lo), "=r"(hi) : "d"(dn));
    lo = 0xFEF311C3u - lo;
    hi = 0xFEF311C3u - hi;
    double r; asm("mov.b64 %0, {%1, %2};" : "=d"(r) : "r"(lo), "r"(hi)); return r;
}

// ---------------------------------------------------------------------------
// Fused projection kernel (fp32 compute; split fp16/fp32 outputs).
//   blocks [0,256):    Wq = Q*W1 + b1     blocks [256,512): Wk = K*W2 + b2
//   e in [0,48) -> half2 arrays (MUFU path); e in [48,64) -> f32 arrays.
// ---------------------------------------------------------------------------
__global__ __launch_bounds__(256) void proj_fused_kernel(
    const float* __restrict__ Q, const float* __restrict__ K,
    const float* __restrict__ W1, const float* __restrict__ b1,
    const float* __restrict__ W2, const float* __restrict__ b2)
{
    __shared__ float Ws[DD][DD];
    __shared__ float Xs[32][DD + 1];

    const int  tid  = threadIdx.x;
    const bool isK  = (blockIdx.x >= 256);
    const int  blk  = isK ? (blockIdx.x - 256) : blockIdx.x;
    const int  rowBase = blk * 32;

    const float* __restrict__ X  = isK ? K  : Q;
    const float* __restrict__ W  = isK ? W2 : W1;
    const float* __restrict__ bb = isK ? b2 : b1;
    __half2* __restrict__ Out16  = isK ? g_Wk16 : g_Wq16;
    float*   __restrict__ Out32  = isK ? g_Wk32 : g_Wq32;

    {
        const float4* src = (const float4*)W;
        float4* dst = (float4*)&Ws[0][0];
#pragma unroll
        for (int t = 0; t < 4; t++) dst[tid + t * 256] = src[tid + t * 256];
    }
#pragma unroll
    for (int t = 0; t < 8; t++) {
        int i = tid + t * 256;
        int r = i >> 6, c = i & 63;
        Xs[r][c] = X[(size_t)(rowBase + r) * DD + c];
    }
    __syncthreads();

    const int lane = tid & 31;
    const int eg   = tid >> 5;

    float acc[8];
#pragma unroll
    for (int j = 0; j < 8; j++) acc[j] = __ldg(&bb[eg * 8 + j]);

#pragma unroll
    for (int d = 0; d < DD; d++) {
        const float xv = Xs[lane][d];
        const float4 w0 = *(const float4*)&Ws[d][eg * 8];
        const float4 w1 = *(const float4*)&Ws[d][eg * 8 + 4];
        acc[0] += xv * w0.x; acc[1] += xv * w0.y;
        acc[2] += xv * w0.z; acc[3] += xv * w0.w;
        acc[4] += xv * w1.x; acc[5] += xv * w1.y;
        acc[6] += xv * w1.z; acc[7] += xv * w1.w;
    }

    __syncthreads();
#pragma unroll
    for (int j = 0; j < 8; j++) Xs[lane][eg * 8 + j] = acc[j];
    __syncthreads();

    // f16 part: 32 rows x 24 half2 = 768
#pragma unroll
    for (int t = 0; t < 3; t++) {
        int i = tid + t * 256;
        int r = i / (D16 / 2), c = i % (D16 / 2);
        Out16[(size_t)(rowBase + r) * (D16 / 2) + c] =
            __floats2half2_rn(Xs[r][2 * c], Xs[r][2 * c + 1]);
    }
    // f32 part: 32 rows x 16 f32 = 512
#pragma unroll
    for (int t = 0; t < 2; t++) {
        int i = tid + t * 256;
        int r = i >> 4, c = i & 15;
        Out32[(size_t)(rowBase + r) * D32 + c] = Xs[r][D16 + c];
    }
}

// ---------------------------------------------------------------------------
// Main kernel: R5 skeleton (32q x 128k tile, 4x4 micro-tile, 1024 blocks)
// with pipe-split tanh:
//   d in [0,48):  f16x2 MUFU tanh path          (pipe: MUFU, binding at 85K cyc)
//   d in [48,64): Pade [5/4] + magic-seed Newton (pipes: FMA+ALU, zero MUFU)
// ---------------------------------------------------------------------------
__global__ __launch_bounds__(256) void attn_main_kernel(
    const float* __restrict__ Vv, const float* __restrict__ bV,
    float* __restrict__ out)
{
    __shared__ unsigned wq16_s[TQ * (D16 / 2)];          // 32 x 24 u32 = 3 KB
    __shared__ unsigned wk16_s[TK * W16];                // 128 x 25 u32 = 12.5 KB
    __shared__ __align__(8) float wq32_s[TQ * W32];      // 32 x 18 f32 = 2.25 KB
    __shared__ __align__(8) float wk32_s[TK * W32];      // 128 x 18 f32 = 9 KB
    __shared__ __half2 v16_s[D16 / 2];
    __shared__ __align__(8) float v32_s[D32];

    const int bh    = blockIdx.z;
    const int qBase = blockIdx.y * TQ;
    const int kBase = blockIdx.x * TK;
    const int tid   = threadIdx.x;

    // ---- fill smem ----
    {
        const unsigned* src = (const unsigned*)(g_Wq16 + (size_t)(bh * LQ + qBase) * (D16 / 2));
#pragma unroll
        for (int t = 0; t < 3; t++)                      // 3*256 = 768 = 32*24
            wq16_s[tid + t * 256] = src[tid + t * 256];
    }
    {
        const unsigned* src = (const unsigned*)(g_Wk16 + (size_t)(bh * LK + kBase) * (D16 / 2));
#pragma unroll
        for (int t = 0; t < 12; t++) {                   // 12*256 = 3072 = 128*24
            int i = tid + t * 256;
            int r = i / (D16 / 2), c = i % (D16 / 2);
            wk16_s[r * W16 + c] = src[i];
        }
    }
    {
        const float* src = g_Wq32 + (size_t)(bh * LQ + qBase) * D32;
#pragma unroll
        for (int t = 0; t < 2; t++) {                    // 2*256 = 512 = 32*16
            int i = tid + t * 256;
            int r = i >> 4, c = i & 15;
            wq32_s[r * W32 + c] = src[i];
        }
    }
    {
        const float* src = g_Wk32 + (size_t)(bh * LK + kBase) * D32;
#pragma unroll
        for (int t = 0; t < 8; t++) {                    // 8*256 = 2048 = 128*16
            int i = tid + t * 256;
            int r = i >> 4, c = i & 15;
            wk32_s[r * W32 + c] = src[i];
        }
    }
    if (tid < D16 / 2) v16_s[tid] = __floats2half2_rn(Vv[2 * tid], Vv[2 * tid + 1]);
    else if (tid >= 32 && tid < 32 + D32) v32_s[tid - 32] = Vv[D16 + (tid - 32)];
    __syncthreads();

    const int ty = tid >> 5;            // warp id -> q rows ty*4 .. ty*4+3
    const int tx = tid & 31;            // k lane; k = j*32 + tx

    double acc[4][4];                   // f32-pair accumulators
#pragma unroll
    for (int i = 0; i < 4; i++)
#pragma unroll
        for (int j = 0; j < 4; j++) acc[i][j] = 0.0;

    // ================= f16x2 MUFU path: d in [0,48), groups of 4 =================
#pragma unroll 4
    for (int c2 = 0; c2 < D16 / 2; c2 += 2) {
        const __half2 v01 = v16_s[c2];
        const __half2 v23 = v16_s[c2 + 1];

        __half2 wq01[4], wq23[4];
#pragma unroll
        for (int i = 0; i < 4; i++) {
            unsigned a = wq16_s[(ty * 4 + i) * (D16 / 2) + c2];       // broadcast
            unsigned b = wq16_s[(ty * 4 + i) * (D16 / 2) + c2 + 1];
            wq01[i] = *(__half2*)&a; wq23[i] = *(__half2*)&b;
        }
        __half2 wk01[4], wk23[4];
#pragma unroll
        for (int j = 0; j < 4; j++) {
            unsigned a = wk16_s[(j * 32 + tx) * W16 + c2];            // conflict-free
            unsigned b = wk16_s[(j * 32 + tx) * W16 + c2 + 1];
            wk01[j] = *(__half2*)&a; wk23[j] = *(__half2*)&b;
        }

#pragma unroll
        for (int i = 0; i < 4; i++)
#pragma unroll
            for (int j = 0; j < 4; j++) {
                __half2 t01 = tanh2(__hadd2(wq01[i], wk01[j]));
                __half2 t23 = tanh2(__hadd2(wq23[i], wk23[j]));
                __half2 h   = __hfma2(t23, v23, __hmul2(t01, v01));
                acc_flush(acc[i][j], h);
            }
    }

    // ================= Pade path: d in [48,64), packed f32 pairs =================
    const double C105  = f2x2(105.0f, 105.0f);
    const double C945  = f2x2(945.0f, 945.0f);
    const double CM15  = f2x2(-15.0f, -15.0f);
    const double CM420 = f2x2(-420.0f, -420.0f);
    const double CM945 = f2x2(-945.0f, -945.0f);
    const double ONE   = f2x2(1.0f, 1.0f);

#pragma unroll 2
    for (int dp = 0; dp < D32 / 2; dp++) {
        const double vp = *(const double*)&v32_s[2 * dp];

        double wqp[4], wkp[4];
#pragma unroll
        for (int i = 0; i < 4; i++)
            wqp[i] = *(const double*)&wq32_s[(ty * 4 + i) * W32 + 2 * dp];  // broadcast
#pragma unroll
        for (int j = 0; j < 4; j++)
            wkp[j] = *(const double*)&wk32_s[(j * 32 + tx) * W32 + 2 * dp]; // half-warp distinct

#pragma unroll
        for (int i = 0; i < 4; i++)
#pragma unroll
            for (int j = 0; j < 4; j++) {
                double x  = addx2(wqp[i], wkp[j]);
                double z  = mulx2(x, x);
                double n  = fmx2(addx2(z, C105), z, C945);        // N = 945+105z+z^2
                double dn = fmx2(fmx2(z, CM15, CM420), z, CM945); // -(945+420z+15z^2)
                double xn = mulx2(x, n);
                double r  = rcp_seed_from_neg(dn);                // ~1/D (ALU)
                r = fmx2(r, fmx2(dn, r, ONE), r);                 // Newton 1
                r = fmx2(r, fmx2(dn, r, ONE), r);                 // Newton 2
                acc[i][j] = fmx2(mulx2(xn, r), vp, acc[i][j]);    // += tanh * v
            }
    }

    // ---- epilogue ----
    const float bv = bV[0];
#pragma unroll
    for (int i = 0; i < 4; i++) {
        const size_t rowOff = (size_t)(bh * LQ + qBase + ty * 4 + i) * LK + kBase;
#pragma unroll
        for (int j = 0; j < 4; j++) {
            float2 a = *(float2*)&acc[i][j];
            out[rowOff + j * 32 + tx] = a.x + a.y + bv;           // coalesced
        }
    }
}

// ---------------------------------------------------------------------------
// Launch
// ---------------------------------------------------------------------------
extern "C" void kernel_launch(void* const* d_in, const int* in_sizes, int n_in,
                              void* d_out, int out_size)
{
    const float* Q  = (const float*)d_in[0];
    const float* K  = (const float*)d_in[1];
    const float* W1 = (const float*)d_in[2];
    const float* b1 = (const float*)d_in[3];
    const float* W2 = (const float*)d_in[4];
    const float* b2 = (const float*)d_in[5];
    const float* V  = (const float*)d_in[6];
    const float* bV = (const float*)d_in[7];
    float* out = (float*)d_out;

    proj_fused_kernel<<<512, 256>>>(Q, K, W1, b1, W2, b2);

    dim3 grid(LK / TK, LQ / TQ, BH);                     // 4 x 16 x 16 = 1024
    attn_main_kernel<<<grid, 256>>>(V, bV, out);
}

// round 8
// speedup vs baseline: 1.0946x; 1.0946x over previous
#include <cuda_runtime.h>
#include <cuda_fp16.h>

#define BH   16
#define LQ   512
#define LK   512
#define DD   64
#define D16  48      // d-slice on MUFU f16x2 tanh path (6 per macro-iter)
#define D32  16      // d-slice on FMA-pipe Pade path   (2 per macro-iter)
#define TQ   32
#define TK   128
#define W16  25      // wk16 row stride in u32 (24 data + 1 pad, odd -> conflict-free)
#define W32  18      // wq32/wk32 row stride in floats (16 data + 2 pad, rows 8B-aligned)

// Projected tensors (device globals: no allocation).
__device__ __half2 g_Wq16[BH * LQ * D16 / 2];
__device__ __half2 g_Wk16[BH * LK * D16 / 2];
__device__ float   g_Wq32[BH * LQ * D32];
__device__ float   g_Wk32[BH * LK * D32];

// ---------------------------------------------------------------------------
// Packed helpers
// ---------------------------------------------------------------------------
__device__ __forceinline__ __half2 tanh2(__half2 x) {
    unsigned xi = *(unsigned*)&x, yi;
    asm("tanh.approx.f16x2 %0, %1;" : "=r"(yi) : "r"(xi));
    return *(__half2*)&yi;
}

__device__ __forceinline__ void acc_flush(double& acc, __half2 h) {
    unsigned hi = *(unsigned*)&h;
    asm("{\n\t"
        ".reg .f16 l, m;\n\t"
        ".reg .f32 fl, fh;\n\t"
        ".reg .b64 p;\n\t"
        "mov.b32 {l, m}, %1;\n\t"
        "cvt.f32.f16 fl, l;\n\t"
        "cvt.f32.f16 fh, m;\n\t"
        "mov.b64 p, {fl, fh};\n\t"
        "add.rn.f32x2 %0, %0, p;\n\t"
        "}" : "+d"(acc) : "r"(hi));
}

__device__ __forceinline__ double f2x2(float lo, float hi) {
    double r; asm("mov.b64 %0, {%1, %2};" : "=d"(r) : "f"(lo), "f"(hi)); return r;
}
__device__ __forceinline__ double addx2(double a, double b) {
    double r; asm("add.rn.f32x2 %0, %1, %2;" : "=d"(r) : "d"(a), "d"(b)); return r;
}
__device__ __forceinline__ double mulx2(double a, double b) {
    double r; asm("mul.rn.f32x2 %0, %1, %2;" : "=d"(r) : "d"(a), "d"(b)); return r;
}
__device__ __forceinline__ double fmx2(double a, double b, double c) {
    double r; asm("fma.rn.f32x2 %0, %1, %2, %3;" : "=d"(r) : "d"(a), "d"(b), "d"(c)); return r;
}
// Reciprocal seed of +D from bits of (-D): 0xFEF311C3 - bits(-D).
__device__ __forceinline__ double rcp_seed_from_neg(double dn) {
    unsigned lo, hi;
    asm("mov.b64 {%0, %1}, %2;" : "=r"(lo), "=r"(hi) : "d"(dn));
    lo = 0xFEF311C3u - lo;
    hi = 0xFEF311C3u - hi;
    double r; asm("mov.b64 %0, {%1, %2};" : "=d"(r) : "r"(lo), "r"(hi)); return r;
}

// ---------------------------------------------------------------------------
// Fused projection kernel (fp32 compute; split fp16/fp32 outputs).
//   blocks [0,256):    Wq = Q*W1 + b1     blocks [256,512): Wk = K*W2 + b2
//   e in [0,48) -> half2 arrays (MUFU path); e in [48,64) -> f32 arrays.
// ---------------------------------------------------------------------------
__global__ __launch_bounds__(256) void proj_fused_kernel(
    const float* __restrict__ Q, const float* __restrict__ K,
    const float* __restrict__ W1, const float* __restrict__ b1,
    const float* __restrict__ W2, const float* __restrict__ b2)
{
    __shared__ float Ws[DD][DD];
    __shared__ float Xs[32][DD + 1];

    const int  tid  = threadIdx.x;
    const bool isK  = (blockIdx.x >= 256);
    const int  blk  = isK ? (blockIdx.x - 256) : blockIdx.x;
    const int  rowBase = blk * 32;

    const float* __restrict__ X  = isK ? K  : Q;
    const float* __restrict__ W  = isK ? W2 : W1;
    const float* __restrict__ bb = isK ? b2 : b1;
    __half2* __restrict__ Out16  = isK ? g_Wk16 : g_Wq16;
    float*   __restrict__ Out32  = isK ? g_Wk32 : g_Wq32;

    {
        const float4* src = (const float4*)W;
        float4* dst = (float4*)&Ws[0][0];
#pragma unroll
        for (int t = 0; t < 4; t++) dst[tid + t * 256] = src[tid + t * 256];
    }
#pragma unroll
    for (int t = 0; t < 8; t++) {
        int i = tid + t * 256;
        int r = i >> 6, c = i & 63;
        Xs[r][c] = X[(size_t)(rowBase + r) * DD + c];
    }
    __syncthreads();

    const int lane = tid & 31;
    const int eg   = tid >> 5;

    float acc[8];
#pragma unroll
    for (int j = 0; j < 8; j++) acc[j] = __ldg(&bb[eg * 8 + j]);

#pragma unroll
    for (int d = 0; d < DD; d++) {
        const float xv = Xs[lane][d];
        const float4 w0 = *(const float4*)&Ws[d][eg * 8];
        const float4 w1 = *(const float4*)&Ws[d][eg * 8 + 4];
        acc[0] += xv * w0.x; acc[1] += xv * w0.y;
        acc[2] += xv * w0.z; acc[3] += xv * w0.w;
        acc[4] += xv * w1.x; acc[5] += xv * w1.y;
        acc[6] += xv * w1.z; acc[7] += xv * w1.w;
    }

    __syncthreads();
#pragma unroll
    for (int j = 0; j < 8; j++) Xs[lane][eg * 8 + j] = acc[j];
    __syncthreads();

    // f16 part: 32 rows x 24 half2 = 768
#pragma unroll
    for (int t = 0; t < 3; t++) {
        int i = tid + t * 256;
        int r = i / (D16 / 2), c = i % (D16 / 2);
        Out16[(size_t)(rowBase + r) * (D16 / 2) + c] =
            __floats2half2_rn(Xs[r][2 * c], Xs[r][2 * c + 1]);
    }
    // f32 part: 32 rows x 16 f32 = 512
#pragma unroll
    for (int t = 0; t < 2; t++) {
        int i = tid + t * 256;
        int r = i >> 4, c = i & 15;
        Out32[(size_t)(rowBase + r) * D32 + c] = Xs[r][D16 + c];
    }
}

// ---------------------------------------------------------------------------
// Main kernel: 32q x 128k tile, 4x4 micro-tile, 1024 blocks.
// SINGLE fused loop (8 macro-iterations), each issuing BOTH
//   - 6 f16 d's through MUFU tanh.f16x2     (MUFU pipe)
//   - 2 f32 d's through Pade[5/4] + Newton  (FMA/ALU pipes, zero MUFU)
// per (q,k), so the pipes overlap instead of running as serial phases.
// ---------------------------------------------------------------------------
__global__ __launch_bounds__(256) void attn_main_kernel(
    const float* __restrict__ Vv, const float* __restrict__ bV,
    float* __restrict__ out)
{
    __shared__ unsigned wq16_s[TQ * (D16 / 2)];          // 32 x 24 u32
    __shared__ unsigned wk16_s[TK * W16];                // 128 x 25 u32 (pad)
    __shared__ __align__(8) float wq32_s[TQ * W32];      // 32 x 18 f32 (pad)
    __shared__ __align__(8) float wk32_s[TK * W32];      // 128 x 18 f32 (pad)
    __shared__ unsigned v16_s[D16 / 2];
    __shared__ __align__(8) float v32_s[D32];

    const int bh    = blockIdx.z;
    const int qBase = blockIdx.y * TQ;
    const int kBase = blockIdx.x * TK;
    const int tid   = threadIdx.x;

    // ---- fill smem ----
    {
        const unsigned* src = (const unsigned*)(g_Wq16 + (size_t)(bh * LQ + qBase) * (D16 / 2));
#pragma unroll
        for (int t = 0; t < 3; t++)                      // 768 = 32*24
            wq16_s[tid + t * 256] = src[tid + t * 256];
    }
    {
        const unsigned* src = (const unsigned*)(g_Wk16 + (size_t)(bh * LK + kBase) * (D16 / 2));
#pragma unroll
        for (int t = 0; t < 12; t++) {                   // 3072 = 128*24
            int i = tid + t * 256;
            int r = i / (D16 / 2), c = i % (D16 / 2);
            wk16_s[r * W16 + c] = src[i];
        }
    }
    {
        const float* src = g_Wq32 + (size_t)(bh * LQ + qBase) * D32;
#pragma unroll
        for (int t = 0; t < 2; t++) {                    // 512 = 32*16
            int i = tid + t * 256;
            int r = i >> 4, c = i & 15;
            wq32_s[r * W32 + c] = src[i];
        }
    }
    {
        const float* src = g_Wk32 + (size_t)(bh * LK + kBase) * D32;
#pragma unroll
        for (int t = 0; t < 8; t++) {                    // 2048 = 128*16
            int i = tid + t * 256;
            int r = i >> 4, c = i & 15;
            wk32_s[r * W32 + c] = src[i];
        }
    }
    if (tid < D16 / 2) {
        __half2 hv = __floats2half2_rn(Vv[2 * tid], Vv[2 * tid + 1]);
        v16_s[tid] = *(unsigned*)&hv;
    } else if (tid >= 32 && tid < 32 + D32) {
        v32_s[tid - 32] = Vv[D16 + (tid - 32)];
    }
    __syncthreads();

    const int ty = tid >> 5;            // warp id -> q rows ty*4 .. ty*4+3
    const int tx = tid & 31;            // k lane; k = j*32 + tx

    double acc[4][4];
#pragma unroll
    for (int i = 0; i < 4; i++)
#pragma unroll
        for (int j = 0; j < 4; j++) acc[i][j] = 0.0;

    const double C105  = f2x2(105.0f, 105.0f);
    const double C945  = f2x2(945.0f, 945.0f);
    const double CM15  = f2x2(-15.0f, -15.0f);
    const double CM420 = f2x2(-420.0f, -420.0f);
    const double CM945 = f2x2(-945.0f, -945.0f);
    const double ONE   = f2x2(1.0f, 1.0f);

    // ================= fused loop: 8 macro-iterations =================
#pragma unroll 2
    for (int s = 0; s < 8; s++) {
        const int c2 = s * 3;           // 3 half2 cols (6 f16 d's)
        const int dp = s;               // 1 f32 pair   (2 Pade d's)

        // f16 operands
        unsigned v0u = v16_s[c2], v1u = v16_s[c2 + 1], v2u = v16_s[c2 + 2];
        const __half2 v0 = *(__half2*)&v0u, v1 = *(__half2*)&v1u, v2 = *(__half2*)&v2u;

        __half2 wqh[4][3], wkh[4][3];
#pragma unroll
        for (int i = 0; i < 4; i++) {
            const unsigned* row = &wq16_s[(ty * 4 + i) * (D16 / 2) + c2];  // broadcast
#pragma unroll
            for (int c = 0; c < 3; c++) { unsigned a = row[c]; wqh[i][c] = *(__half2*)&a; }
        }
#pragma unroll
        for (int j = 0; j < 4; j++) {
            const unsigned* row = &wk16_s[(j * 32 + tx) * W16 + c2];       // conflict-free
#pragma unroll
            for (int c = 0; c < 3; c++) { unsigned a = row[c]; wkh[j][c] = *(__half2*)&a; }
        }

        // Pade operands
        const double vp = *(const double*)&v32_s[2 * dp];
        double wqp[4], wkp[4];
#pragma unroll
        for (int i = 0; i < 4; i++)
            wqp[i] = *(const double*)&wq32_s[(ty * 4 + i) * W32 + 2 * dp];
#pragma unroll
        for (int j = 0; j < 4; j++)
            wkp[j] = *(const double*)&wk32_s[(j * 32 + tx) * W32 + 2 * dp];

        // Both paths per (q,k) in one body -> MUFU + FMA interleave
#pragma unroll
        for (int i = 0; i < 4; i++) {
#pragma unroll
            for (int j = 0; j < 4; j++) {
                // -- MUFU path (6 d's) --
                __half2 t0 = tanh2(__hadd2(wqh[i][0], wkh[j][0]));
                __half2 t1 = tanh2(__hadd2(wqh[i][1], wkh[j][1]));
                __half2 t2 = tanh2(__hadd2(wqh[i][2], wkh[j][2]));

                // -- Pade path (2 d's), zero MUFU --
                double x  = addx2(wqp[i], wkp[j]);
                double z  = mulx2(x, x);
                double n  = fmx2(addx2(z, C105), z, C945);
                double dn = fmx2(fmx2(z, CM15, CM420), z, CM945);
                double xn = mulx2(x, n);
                double r  = rcp_seed_from_neg(dn);
                r = fmx2(r, fmx2(dn, r, ONE), r);
                r = fmx2(r, fmx2(dn, r, ONE), r);

                __half2 h = __hmul2(t0, v0);
                h = __hfma2(t1, v1, h);
                h = __hfma2(t2, v2, h);
                acc_flush(acc[i][j], h);

                acc[i][j] = fmx2(mulx2(xn, r), vp, acc[i][j]);
            }
        }
    }

    // ---- epilogue ----
    const float bv = bV[0];
#pragma unroll
    for (int i = 0; i < 4; i++) {
        const size_t rowOff = (size_t)(bh * LQ + qBase + ty * 4 + i) * LK + kBase;
#pragma unroll
        for (int j = 0; j < 4; j++) {
            float2 a = *(float2*)&acc[i][j];
            out[rowOff + j * 32 + tx] = a.x + a.y + bv;      // coalesced
        }
    }
}

// ---------------------------------------------------------------------------
// Launch
// ---------------------------------------------------------------------------
extern "C" void kernel_launch(void* const* d_in, const int* in_sizes, int n_in,
                              void* d_out, int out_size)
{
    const float* Q  = (const float*)d_in[0];
    const float* K  = (const float*)d_in[1];
    const float* W1 = (const float*)d_in[2];
    const float* b1 = (const float*)d_in[3];
    const float* W2 = (const float*)d_in[4];
    const float* b2 = (const float*)d_in[5];
    const float* V  = (const float*)d_in[6];
    const float* bV = (const float*)d_in[7];
    float* out = (float*)d_out;

    proj_fused_kernel<<<512, 256>>>(Q, K, W1, b1, W2, b2);

    dim3 grid(LK / TK, LQ / TQ, BH);                     // 4 x 16 x 16 = 1024
    attn_main_kernel<<<grid, 256>>>(V, bV, out);
}

// round 10
// speedup vs baseline: 1.2555x; 1.1470x over previous
#include <cuda_runtime.h>

#define BH    16
#define LQ    512
#define LK    512
#define DD    64
#define DMUFU 36     // d in [0,36): raw values, MUFU tanh path (18 pairs)
#define NP_M  18
#define NP_F  14     // d in [36,64): pre-tanh'd, addition-formula path (14 pairs)
#define TQ    16
#define TK    128
#define WPD   66     // smem row stride in floats: 8B-aligned, LDS.64 conflict-free

// Projected tensors, f32 [row][64]:
//   g_Wq: cols 0..35 = raw wq,  cols 36..63 = tanh(wq)
//   g_Wk: cols 0..35 = raw wk,  cols 36..63 = -tanh(wk)
__device__ float g_Wq[BH * LQ * DD];
__device__ float g_Wk[BH * LK * DD];

// ---------------------------------------------------------------------------
// Helpers
// ---------------------------------------------------------------------------
__device__ __forceinline__ float tanhapx(float x) {
    float y; asm("tanh.approx.f32 %0, %1;" : "=f"(y) : "f"(x)); return y;
}
__device__ __forceinline__ double f2x2(float lo, float hi) {
    double r; asm("mov.b64 %0, {%1, %2};" : "=d"(r) : "f"(lo), "f"(hi)); return r;
}
__device__ __forceinline__ void unpack2(double p, float& lo, float& hi) {
    asm("mov.b64 {%0, %1}, %2;" : "=f"(lo), "=f"(hi) : "d"(p));
}
__device__ __forceinline__ double addx2(double a, double b) {
    double r; asm("add.rn.f32x2 %0, %1, %2;" : "=d"(r) : "d"(a), "d"(b)); return r;
}
__device__ __forceinline__ double mulx2(double a, double b) {
    double r; asm("mul.rn.f32x2 %0, %1, %2;" : "=d"(r) : "d"(a), "d"(b)); return r;
}
__device__ __forceinline__ double fmx2(double a, double b, double c) {
    double r; asm("fma.rn.f32x2 %0, %1, %2, %3;" : "=d"(r) : "d"(a), "d"(b), "d"(c)); return r;
}
// Reciprocal seed of +D from bits of (-D): 0xFEF311C3 - bits(-D). D > 0.
__device__ __forceinline__ double rcp_seed_from_neg(double dn) {
    unsigned lo, hi;
    asm("mov.b64 {%0, %1}, %2;" : "=r"(lo), "=r"(hi) : "d"(dn));
    lo = 0xFEF311C3u - lo;
    hi = 0xFEF311C3u - hi;
    double r; asm("mov.b64 %0, {%1, %2};" : "=d"(r) : "r"(lo), "r"(hi)); return r;
}

// ---------------------------------------------------------------------------
// Fused projection kernel (fp32).
//   blocks [0,256):    Wq = Q*W1 + b1 ; cols 36..63 -> tanh
//   blocks [256,512):  Wk = K*W2 + b2 ; cols 36..63 -> -tanh
// ---------------------------------------------------------------------------
__global__ __launch_bounds__(256) void proj_fused_kernel(
    const float* __restrict__ Q, const float* __restrict__ K,
    const float* __restrict__ W1, const float* __restrict__ b1,
    const float* __restrict__ W2, const float* __restrict__ b2)
{
    __shared__ float Ws[DD][DD];
    __shared__ float Xs[32][DD + 1];

    const int  tid  = threadIdx.x;
    const bool isK  = (blockIdx.x >= 256);
    const int  blk  = isK ? (blockIdx.x - 256) : blockIdx.x;
    const int  rowBase = blk * 32;

    const float* __restrict__ X  = isK ? K  : Q;
    const float* __restrict__ W  = isK ? W2 : W1;
    const float* __restrict__ bb = isK ? b2 : b1;
    float* __restrict__ Out      = isK ? g_Wk : g_Wq;

    {
        const float4* src = (const float4*)W;
        float4* dst = (float4*)&Ws[0][0];
#pragma unroll
        for (int t = 0; t < 4; t++) dst[tid + t * 256] = src[tid + t * 256];
    }
#pragma unroll
    for (int t = 0; t < 8; t++) {
        int i = tid + t * 256;
        int r = i >> 6, c = i & 63;
        Xs[r][c] = X[(size_t)(rowBase + r) * DD + c];
    }
    __syncthreads();

    const int lane = tid & 31;
    const int eg   = tid >> 5;    // e-group: e = eg*8 + j

    float acc[8];
#pragma unroll
    for (int j = 0; j < 8; j++) acc[j] = __ldg(&bb[eg * 8 + j]);

#pragma unroll
    for (int d = 0; d < DD; d++) {
        const float xv = Xs[lane][d];
        const float4 w0 = *(const float4*)&Ws[d][eg * 8];
        const float4 w1 = *(const float4*)&Ws[d][eg * 8 + 4];
        acc[0] += xv * w0.x; acc[1] += xv * w0.y;
        acc[2] += xv * w0.z; acc[3] += xv * w0.w;
        acc[4] += xv * w1.x; acc[5] += xv * w1.y;
        acc[6] += xv * w1.z; acc[7] += xv * w1.w;
    }

    // Transform cols >= DMUFU: tanh (Q) or -tanh (K)
    {
        const float sgn = isK ? -1.0f : 1.0f;
#pragma unroll
        for (int j = 0; j < 8; j++)
            if (eg * 8 + j >= DMUFU) acc[j] = sgn * tanhapx(acc[j]);
    }

    __syncthreads();
#pragma unroll
    for (int j = 0; j < 8; j++) Xs[lane][eg * 8 + j] = acc[j];
    __syncthreads();
#pragma unroll
    for (int t = 0; t < 8; t++) {
        int i = tid + t * 256;
        int r = i >> 6, c = i & 63;
        Out[(size_t)(rowBase + r) * DD + c] = Xs[r][c];     // coalesced
    }
}

// ---------------------------------------------------------------------------
// Main kernel: tile 16q x 128k, micro-tile 2x4, 2048 blocks, 3 CTAs/SM.
//   14 fused iterations: 1 MUFU d-pair + 1 formula d-pair per (q,k) body
//     MUFU:    addx2 -> 2x tanh.approx.f32 -> packed fma x v   (16 MUFU cyc)
//     formula: tanh(a+b)=(tq+tk)/(1+tq*tk), magic seed + 2 Newton (16 FMA cyc)
//   + 4 MUFU-only iterations (pairs 14..17).
// Per-SMSP budget: MUFU 63.8K cyc ~= FMA 65.5K cyc (balanced).
// ---------------------------------------------------------------------------
__global__ __launch_bounds__(256, 3) void attn_main_kernel(
    const float* __restrict__ Vv, const float* __restrict__ bV,
    float* __restrict__ out)
{
    __shared__ __align__(8) float wq_s[TQ][WPD];    // 16 x 66
    __shared__ __align__(8) float wk_s[TK][WPD];    // 128 x 66
    __shared__ __align__(8) float v_s[DD];

    const int bh    = blockIdx.z;
    const int qBase = blockIdx.y * TQ;
    const int kBase = blockIdx.x * TK;
    const int tid   = threadIdx.x;

    // ---- fill smem (coalesced global reads, padded stores) ----
    {
        const float* src = g_Wq + (size_t)(bh * LQ + qBase) * DD;
#pragma unroll
        for (int t = 0; t < 4; t++) {                 // 1024 = 16*64
            int i = tid + t * 256;
            wq_s[i >> 6][i & 63] = src[i];
        }
    }
    {
        const float* src = g_Wk + (size_t)(bh * LK + kBase) * DD;
#pragma unroll
        for (int t = 0; t < 32; t++) {                // 8192 = 128*64
            int i = tid + t * 256;
            wk_s[i >> 6][i & 63] = src[i];
        }
    }
    if (tid < DD) v_s[tid] = Vv[tid];
    __syncthreads();

    const int ty = tid >> 5;          // warp id -> q rows ty*2, ty*2+1
    const int tx = tid & 31;          // k lane; k = j*32 + tx

    double acc[2][4];
#pragma unroll
    for (int i = 0; i < 2; i++)
#pragma unroll
        for (int j = 0; j < 4; j++) acc[i][j] = 0.0;

    const double ONE  = f2x2(1.0f, 1.0f);
    const double MONE = f2x2(-1.0f, -1.0f);

    // ======== fused iterations: MUFU pair s + formula pair s ========
#pragma unroll 2
    for (int s = 0; s < NP_F; s++) {
        const int cm = 2 * s;                 // MUFU cols
        const int cf = DMUFU + 2 * s;         // formula cols
        const double vm = *(const double*)&v_s[cm];
        const double vp = *(const double*)&v_s[cf];

        double wkm[4], ntk[4];
#pragma unroll
        for (int j = 0; j < 4; j++) {
            wkm[j] = *(const double*)&wk_s[j * 32 + tx][cm];   // conflict-free
            ntk[j] = *(const double*)&wk_s[j * 32 + tx][cf];
        }

#pragma unroll
        for (int i = 0; i < 2; i++) {
            const double wqm = *(const double*)&wq_s[ty * 2 + i][cm];   // broadcast
            const double tq  = *(const double*)&wq_s[ty * 2 + i][cf];

#pragma unroll
            for (int j = 0; j < 4; j++) {
                // ---- MUFU path (2 d's) ----
                double x = addx2(wqm, wkm[j]);
                float xlo, xhi;
                unpack2(x, xlo, xhi);
                double tp = f2x2(tanhapx(xlo), tanhapx(xhi));
                acc[i][j] = fmx2(tp, vm, acc[i][j]);

                // ---- addition-formula path (2 d's), zero MUFU ----
                double num  = fmx2(ntk[j], MONE, tq);      // tq + tk
                double nden = fmx2(tq, ntk[j], MONE);      // -(1 + tq*tk) < 0
                double r    = rcp_seed_from_neg(nden);     // ~1/den (ALU)
                r = fmx2(r, fmx2(nden, r, ONE), r);        // Newton 1
                r = fmx2(r, fmx2(nden, r, ONE), r);        // Newton 2
                acc[i][j] = fmx2(mulx2(num, r), vp, acc[i][j]);
            }
        }
    }

    // ======== MUFU-only iterations: pairs 14..17 ========
#pragma unroll
    for (int s = NP_F; s < NP_M; s++) {
        const int cm = 2 * s;
        const double vm = *(const double*)&v_s[cm];

        double wkm[4];
#pragma unroll
        for (int j = 0; j < 4; j++)
            wkm[j] = *(const double*)&wk_s[j * 32 + tx][cm];

#pragma unroll
        for (int i = 0; i < 2; i++) {
            const double wqm = *(const double*)&wq_s[ty * 2 + i][cm];
#pragma unroll
            for (int j = 0; j < 4; j++) {
                double x = addx2(wqm, wkm[j]);
                float xlo, xhi;
                unpack2(x, xlo, xhi);
                double tp = f2x2(tanhapx(xlo), tanhapx(xhi));
                acc[i][j] = fmx2(tp, vm, acc[i][j]);
            }
        }
    }

    // ---- epilogue ----
    const float bv = bV[0];
#pragma unroll
    for (int i = 0; i < 2; i++) {
        const size_t rowOff = (size_t)(bh * LQ + qBase + ty * 2 + i) * LK + kBase;
#pragma unroll
        for (int j = 0; j < 4; j++) {
            float lo, hi;
            unpack2(acc[i][j], lo, hi);
            out[rowOff + j * 32 + tx] = lo + hi + bv;      // coalesced
        }
    }
}

// ---------------------------------------------------------------------------
// Launch
// ---------------------------------------------------------------------------
extern "C" void kernel_launch(void* const* d_in, const int* in_sizes, int n_in,
                              void* d_out, int out_size)
{
    const float* Q  = (const float*)d_in[0];
    const float* K  = (const float*)d_in[1];
    const float* W1 = (const float*)d_in[2];
    const float* b1 = (const float*)d_in[3];
    const float* W2 = (const float*)d_in[4];
    const float* b2 = (const float*)d_in[5];
    const float* V  = (const float*)d_in[6];
    const float* bV = (const float*)d_in[7];
    float* out = (float*)d_out;

    proj_fused_kernel<<<512, 256>>>(Q, K, W1, b1, W2, b2);

    dim3 grid(LK / TK, LQ / TQ, BH);                  // 4 x 32 x 16 = 2048
    attn_main_kernel<<<grid, 256>>>(V, bV, out);
}

// round 11
// speedup vs baseline: 1.2624x; 1.0055x over previous
#include <cuda_runtime.h>

#define BH    16
#define LQ    512
#define LK    512
#define DD    64
#define DMUFU 36     // d in [0,36): raw values, MUFU tanh path
#define TQ    16
#define TK    128
#define WPD   68     // smem row stride in floats: 272B, 16B-aligned, LDS.128 conflict-free

// Projected tensors, f32 [row][64]:
//   g_Wq: cols 0..35 = raw wq,  cols 36..63 = tanh(wq)
//   g_Wk: cols 0..35 = raw wk,  cols 36..63 = -tanh(wk)
__device__ float g_Wq[BH * LQ * DD];
__device__ float g_Wk[BH * LK * DD];

// ---------------------------------------------------------------------------
// Helpers
// ---------------------------------------------------------------------------
__device__ __forceinline__ float tanhapx(float x) {
    float y; asm("tanh.approx.f32 %0, %1;" : "=f"(y) : "f"(x)); return y;
}
__device__ __forceinline__ double f2x2(float lo, float hi) {
    double r; asm("mov.b64 %0, {%1, %2};" : "=d"(r) : "f"(lo), "f"(hi)); return r;
}
__device__ __forceinline__ void unpack2(double p, float& lo, float& hi) {
    asm("mov.b64 {%0, %1}, %2;" : "=f"(lo), "=f"(hi) : "d"(p));
}
__device__ __forceinline__ double addx2(double a, double b) {
    double r; asm("add.rn.f32x2 %0, %1, %2;" : "=d"(r) : "d"(a), "d"(b)); return r;
}
__device__ __forceinline__ double mulx2(double a, double b) {
    double r; asm("mul.rn.f32x2 %0, %1, %2;" : "=d"(r) : "d"(a), "d"(b)); return r;
}
__device__ __forceinline__ double fmx2(double a, double b, double c) {
    double r; asm("fma.rn.f32x2 %0, %1, %2, %3;" : "=d"(r) : "d"(a), "d"(b), "d"(c)); return r;
}
// Reciprocal seed of +D from bits of (-D): 0xFEF311C3 - bits(-D). D > 0.
__device__ __forceinline__ double rcp_seed_from_neg(double dn) {
    unsigned lo, hi;
    asm("mov.b64 {%0, %1}, %2;" : "=r"(lo), "=r"(hi) : "d"(dn));
    lo = 0xFEF311C3u - lo;
    hi = 0xFEF311C3u - hi;
    double r; asm("mov.b64 %0, {%1, %2};" : "=d"(r) : "r"(lo), "r"(hi)); return r;
}

// ---------------------------------------------------------------------------
// Fused projection kernel (fp32).
//   blocks [0,256):    Wq = Q*W1 + b1 ; cols 36..63 -> tanh
//   blocks [256,512):  Wk = K*W2 + b2 ; cols 36..63 -> -tanh
// ---------------------------------------------------------------------------
__global__ __launch_bounds__(256) void proj_fused_kernel(
    const float* __restrict__ Q, const float* __restrict__ K,
    const float* __restrict__ W1, const float* __restrict__ b1,
    const float* __restrict__ W2, const float* __restrict__ b2)
{
    __shared__ float Ws[DD][DD];
    __shared__ float Xs[32][DD + 1];

    const int  tid  = threadIdx.x;
    const bool isK  = (blockIdx.x >= 256);
    const int  blk  = isK ? (blockIdx.x - 256) : blockIdx.x;
    const int  rowBase = blk * 32;

    const float* __restrict__ X  = isK ? K  : Q;
    const float* __restrict__ W  = isK ? W2 : W1;
    const float* __restrict__ bb = isK ? b2 : b1;
    float* __restrict__ Out      = isK ? g_Wk : g_Wq;

    {
        const float4* src = (const float4*)W;
        float4* dst = (float4*)&Ws[0][0];
#pragma unroll
        for (int t = 0; t < 4; t++) dst[tid + t * 256] = src[tid + t * 256];
    }
#pragma unroll
    for (int t = 0; t < 8; t++) {
        int i = tid + t * 256;
        int r = i >> 6, c = i & 63;
        Xs[r][c] = X[(size_t)(rowBase + r) * DD + c];
    }
    __syncthreads();

    const int lane = tid & 31;
    const int eg   = tid >> 5;    // e-group: e = eg*8 + j

    float acc[8];
#pragma unroll
    for (int j = 0; j < 8; j++) acc[j] = __ldg(&bb[eg * 8 + j]);

#pragma unroll
    for (int d = 0; d < DD; d++) {
        const float xv = Xs[lane][d];
        const float4 w0 = *(const float4*)&Ws[d][eg * 8];
        const float4 w1 = *(const float4*)&Ws[d][eg * 8 + 4];
        acc[0] += xv * w0.x; acc[1] += xv * w0.y;
        acc[2] += xv * w0.z; acc[3] += xv * w0.w;
        acc[4] += xv * w1.x; acc[5] += xv * w1.y;
        acc[6] += xv * w1.z; acc[7] += xv * w1.w;
    }

    // Transform cols >= DMUFU: tanh (Q) or -tanh (K)
    {
        const float sgn = isK ? -1.0f : 1.0f;
#pragma unroll
        for (int j = 0; j < 8; j++)
            if (eg * 8 + j >= DMUFU) acc[j] = sgn * tanhapx(acc[j]);
    }

    __syncthreads();
#pragma unroll
    for (int j = 0; j < 8; j++) Xs[lane][eg * 8 + j] = acc[j];
    __syncthreads();
#pragma unroll
    for (int t = 0; t < 8; t++) {
        int i = tid + t * 256;
        int r = i >> 6, c = i & 63;
        Out[(size_t)(rowBase + r) * DD + c] = Xs[r][c];     // coalesced
    }
}

// ---------------------------------------------------------------------------
// Main kernel: 128-thread blocks, tile 16q x 128k, micro-tile 4x4 per warp,
// 5 CTAs/SM. Fused loop in steps of 4 d's per path:
//   MUFU:    addx2 -> tanh.approx.f32 x2 -> packed fma  (d 0..27 fused, 28..35 tail)
//   formula: tanh(a+b)=(tq+tk)/(1+tq*tk), magic seed + 2 Newton (d 36..63)
// LDS.128 tile loads (stride 68 -> conflict-free), wq loads broadcast.
// ---------------------------------------------------------------------------
__global__ __launch_bounds__(128, 5) void attn_main_kernel(
    const float* __restrict__ Vv, const float* __restrict__ bV,
    float* __restrict__ out)
{
    __shared__ __align__(16) float wq_s[TQ][WPD];    // 16 x 68
    __shared__ __align__(16) float wk_s[TK][WPD];    // 128 x 68
    __shared__ __align__(16) float v_s[DD];

    const int bh    = blockIdx.z;
    const int qBase = blockIdx.y * TQ;
    const int kBase = blockIdx.x * TK;
    const int tid   = threadIdx.x;

    // ---- fill smem (coalesced global reads, padded stores) ----
    {
        const float* src = g_Wq + (size_t)(bh * LQ + qBase) * DD;
#pragma unroll
        for (int t = 0; t < 8; t++) {                 // 1024 = 16*64
            int i = tid + t * 128;
            wq_s[i >> 6][i & 63] = src[i];
        }
    }
    {
        const float* src = g_Wk + (size_t)(bh * LK + kBase) * DD;
#pragma unroll
        for (int t = 0; t < 64; t++) {                // 8192 = 128*64
            int i = tid + t * 128;
            wk_s[i >> 6][i & 63] = src[i];
        }
    }
    if (tid < DD) v_s[tid] = Vv[tid];
    __syncthreads();

    const int ty = tid >> 5;          // warp id (0..3) -> q rows ty*4 .. ty*4+3
    const int tx = tid & 31;          // k lane; k = j*32 + tx

    double acc[4][4];
#pragma unroll
    for (int i = 0; i < 4; i++)
#pragma unroll
        for (int j = 0; j < 4; j++) acc[i][j] = 0.0;

    const double ONE  = f2x2(1.0f, 1.0f);
    const double MONE = f2x2(-1.0f, -1.0f);

    // ======== fused: 7 iterations x (4 MUFU d's + 4 formula d's) ========
#pragma unroll 1
    for (int s2 = 0; s2 < 7; s2++) {
        const int cm = 4 * s2;            // MUFU cols cm..cm+3   (0..27)
        const int cf = DMUFU + 4 * s2;    // formula cols cf..cf+3 (36..63)

        const float4 vmf = *(const float4*)&v_s[cm];
        const float4 vff = *(const float4*)&v_s[cf];
        const double vm0 = f2x2(vmf.x, vmf.y), vm1 = f2x2(vmf.z, vmf.w);
        const double vf0 = f2x2(vff.x, vff.y), vf1 = f2x2(vff.z, vff.w);

        float4 wkm4[4], wkf4[4];
#pragma unroll
        for (int j = 0; j < 4; j++) {
            wkm4[j] = *(const float4*)&wk_s[j * 32 + tx][cm];   // LDS.128 conflict-free
            wkf4[j] = *(const float4*)&wk_s[j * 32 + tx][cf];
        }

#pragma unroll
        for (int i = 0; i < 4; i++) {
            const float4 wqm4 = *(const float4*)&wq_s[ty * 4 + i][cm];   // broadcast
            const float4 wqf4 = *(const float4*)&wq_s[ty * 4 + i][cf];
            const double wqm0 = f2x2(wqm4.x, wqm4.y), wqm1 = f2x2(wqm4.z, wqm4.w);
            const double tq0  = f2x2(wqf4.x, wqf4.y), tq1  = f2x2(wqf4.z, wqf4.w);

#pragma unroll
            for (int j = 0; j < 4; j++) {
                // ---- MUFU path: 4 d's ----
                double x0 = addx2(wqm0, f2x2(wkm4[j].x, wkm4[j].y));
                double x1 = addx2(wqm1, f2x2(wkm4[j].z, wkm4[j].w));
                float a0, a1, a2, a3;
                unpack2(x0, a0, a1);
                unpack2(x1, a2, a3);
                double t0 = f2x2(tanhapx(a0), tanhapx(a1));
                double t1 = f2x2(tanhapx(a2), tanhapx(a3));
                acc[i][j] = fmx2(t0, vm0, acc[i][j]);
                acc[i][j] = fmx2(t1, vm1, acc[i][j]);

                // ---- formula path: 4 d's, zero MUFU ----
                const double ntk0 = f2x2(wkf4[j].x, wkf4[j].y);
                const double ntk1 = f2x2(wkf4[j].z, wkf4[j].w);

                double num0  = fmx2(ntk0, MONE, tq0);      // tq + tk
                double nden0 = fmx2(tq0, ntk0, MONE);      // -(1 + tq*tk)
                double r0    = rcp_seed_from_neg(nden0);
                r0 = fmx2(r0, fmx2(nden0, r0, ONE), r0);   // Newton 1
                r0 = fmx2(r0, fmx2(nden0, r0, ONE), r0);   // Newton 2
                acc[i][j] = fmx2(mulx2(num0, r0), vf0, acc[i][j]);

                double num1  = fmx2(ntk1, MONE, tq1);
                double nden1 = fmx2(tq1, ntk1, MONE);
                double r1    = rcp_seed_from_neg(nden1);
                r1 = fmx2(r1, fmx2(nden1, r1, ONE), r1);
                r1 = fmx2(r1, fmx2(nden1, r1, ONE), r1);
                acc[i][j] = fmx2(mulx2(num1, r1), vf1, acc[i][j]);
            }
        }
    }

    // ======== MUFU-only tail: cols 28..35 (2 iterations of 4 d's) ========
#pragma unroll
    for (int s2 = 7; s2 < 9; s2++) {
        const int cm = 4 * s2;            // 28, 32
        const float4 vmf = *(const float4*)&v_s[cm];
        const double vm0 = f2x2(vmf.x, vmf.y), vm1 = f2x2(vmf.z, vmf.w);

        float4 wkm4[4];
#pragma unroll
        for (int j = 0; j < 4; j++)
            wkm4[j] = *(const float4*)&wk_s[j * 32 + tx][cm];

#pragma unroll
        for (int i = 0; i < 4; i++) {
            const float4 wqm4 = *(const float4*)&wq_s[ty * 4 + i][cm];
            const double wqm0 = f2x2(wqm4.x, wqm4.y), wqm1 = f2x2(wqm4.z, wqm4.w);
#pragma unroll
            for (int j = 0; j < 4; j++) {
                double x0 = addx2(wqm0, f2x2(wkm4[j].x, wkm4[j].y));
                double x1 = addx2(wqm1, f2x2(wkm4[j].z, wkm4[j].w));
                float a0, a1, a2, a3;
                unpack2(x0, a0, a1);
                unpack2(x1, a2, a3);
                double t0 = f2x2(tanhapx(a0), tanhapx(a1));
                double t1 = f2x2(tanhapx(a2), tanhapx(a3));
                acc[i][j] = fmx2(t0, vm0, acc[i][j]);
                acc[i][j] = fmx2(t1, vm1, acc[i][j]);
            }
        }
    }

    // ---- epilogue ----
    const float bv = bV[0];
#pragma unroll
    for (int i = 0; i < 4; i++) {
        const size_t rowOff = (size_t)(bh * LQ + qBase + ty * 4 + i) * LK + kBase;
#pragma unroll
        for (int j = 0; j < 4; j++) {
            float lo, hi;
            unpack2(acc[i][j], lo, hi);
            out[rowOff + j * 32 + tx] = lo + hi + bv;      // coalesced
        }
    }
}

// ---------------------------------------------------------------------------
// Launch
// ---------------------------------------------------------------------------
extern "C" void kernel_launch(void* const* d_in, const int* in_sizes, int n_in,
                              void* d_out, int out_size)
{
    const float* Q  = (const float*)d_in[0];
    const float* K  = (const float*)d_in[1];
    const float* W1 = (const float*)d_in[2];
    const float* b1 = (const float*)d_in[3];
    const float* W2 = (const float*)d_in[4];
    const float* b2 = (const float*)d_in[5];
    const float* V  = (const float*)d_in[6];
    const float* bV = (const float*)d_in[7];
    float* out = (float*)d_out;

    proj_fused_kernel<<<512, 256>>>(Q, K, W1, b1, W2, b2);

    dim3 grid(LK / TK, LQ / TQ, BH);                  // 4 x 32 x 16 = 2048
    attn_main_kernel<<<grid, 128>>>(V, bV, out);
}